// round 14
// baseline (speedup 1.0000x reference)
#include <cuda_runtime.h>
#include <cuda_bf16.h>
#include <math.h>
#include <stdint.h>

// ---------------------------------------------------------------------------
// ViT attention: TF32 mma.sync, pre-rounded tf32 operands, sigma-permuted
// Q/K head-dim layouts, V stored transposed [B][E][S] with sigma-permuted s
// (all attention fragment loads vectorized + conflict-free), fragment-major
// P staging with per-group named barriers, single-sync cp.async pipelines.
// B=4, S=2048, E=768, H=12, D=64.
// d_out = attn_output [4,2048,768] ++ attn_weights [4,12,2048,2048].
// ---------------------------------------------------------------------------

#define BATCH     4
#define SEQ       2048
#define EMB       768
#define HEADS     12
#define HDIM      64
#define MTOK      (BATCH * SEQ)
#define BH        (BATCH * HEADS)
#define SCALE_F   0.125f

#define PAD       36      // projection smem stride (LDS.32 conflict-free)
#define KSTR      72      // K tile stride (conflict-free LDS.64)
#define VSTR      72      // V^T tile stride (conflict-free LDS.64)
#define PSBLK     132     // Ps words per (mt,chunk) block

// Scratch (device globals). All tf32-rounded.
// g_q/g_k sigma-permuted along d. g_v TRANSPOSED: [B][EMB][SEQ], s sigma'd.
__device__ float g_q[MTOK * EMB];
__device__ float g_k[MTOK * EMB];
__device__ float g_v[MTOK * EMB];
__device__ float g_att[MTOK * EMB];
__device__ float g_inv[BH * SEQ];
__device__ float g_hsr[MTOK * EMB];
__device__ float g_wq[EMB * EMB];
__device__ float g_wk[EMB * EMB];
__device__ float g_wv[EMB * EMB];
__device__ float g_wo[EMB * EMB];

// ---------------------------------------------------------------------------
__device__ __forceinline__ void cp16(void* s, const void* g) {
    uint32_t sa = (uint32_t)__cvta_generic_to_shared(s);
    asm volatile("cp.async.cg.shared.global [%0], [%1], 16;\n" :: "r"(sa), "l"(g));
}
__device__ __forceinline__ void cp_commit() {
    asm volatile("cp.async.commit_group;\n" ::: "memory");
}
__device__ __forceinline__ void cp_wait1() {
    asm volatile("cp.async.wait_group 1;\n" ::: "memory");
}
__device__ __forceinline__ void cp_wait0() {
    asm volatile("cp.async.wait_group 0;\n" ::: "memory");
}

__device__ __forceinline__ float rnd(float x) {
    float r;
    asm("cvt.rna.tf32.f32 %0, %1;" : "=f"(r) : "f"(x));
    return r;
}
__device__ __forceinline__ uint32_t raw(float x) { return __float_as_uint(x); }

__device__ __forceinline__ void mma_tf32(float c[4],
                                         uint32_t a0, uint32_t a1, uint32_t a2, uint32_t a3,
                                         uint32_t b0, uint32_t b1) {
    asm volatile(
        "mma.sync.aligned.m16n8k8.row.col.f32.tf32.tf32.f32 "
        "{%0,%1,%2,%3}, {%4,%5,%6,%7}, {%8,%9}, {%0,%1,%2,%3};\n"
        : "+f"(c[0]), "+f"(c[1]), "+f"(c[2]), "+f"(c[3])
        : "r"(a0), "r"(a1), "r"(a2), "r"(a3), "r"(b0), "r"(b1));
}

// ---------------------------------------------------------------------------
// Fused pre-round: hs + 4 weight matrices in one launch.
// ---------------------------------------------------------------------------
__global__ void round_all_kernel(const float4* __restrict__ hs,
                                 const float4* __restrict__ wq,
                                 const float4* __restrict__ wk,
                                 const float4* __restrict__ wv,
                                 const float4* __restrict__ wo,
                                 float4* __restrict__ dhsr,
                                 float4* __restrict__ dwq,
                                 float4* __restrict__ dwk,
                                 float4* __restrict__ dwv,
                                 float4* __restrict__ dwo,
                                 int n4_hs, int n4_w) {
    int i = blockIdx.x * blockDim.x + threadIdx.x;
    const float4* in;
    float4* out;
    int j = i;
    if (j < n4_hs)            { in = hs; out = dhsr; }
    else if ((j -= n4_hs) < n4_w)  { in = wq; out = dwq; }
    else if ((j -= n4_w) < n4_w)   { in = wk; out = dwk; }
    else if ((j -= n4_w) < n4_w)   { in = wv; out = dwv; }
    else if ((j -= n4_w) < n4_w)   { in = wo; out = dwo; }
    else return;
    float4 v = in[j];
    v.x = rnd(v.x); v.y = rnd(v.y); v.z = rnd(v.z); v.w = rnd(v.w);
    out[j] = v;
}

// ---------------------------------------------------------------------------
// Shared GEMM mainloop body.
// Epilogue mode: 0 plain fp32, 1 rounded+sigma(n) (g_q/g_k),
//                2 rounded TRANSPOSED + sigma(s) (g_v as [B][E][S]).
// ---------------------------------------------------------------------------
__device__ __forceinline__ void gemm_body(const float* __restrict__ A,
                                          const float* __restrict__ W,
                                          const float* __restrict__ bias,
                                          float* __restrict__ C,
                                          int M, int N, int K,
                                          int m0, int n0, int mode,
                                          float* sm) {
    float (*As)[128][PAD] = (float (*)[128][PAD])sm;
    float (*Ws)[128][PAD] = (float (*)[128][PAD])(sm + 3 * 128 * PAD);

    const int tid = threadIdx.x;
    const int wid = tid >> 5;
    const int lane = tid & 31;
    const int wm = (wid >> 1) * 32;
    const int wn = (wid & 1) * 64;
    const int g = lane >> 2;
    const int t = lane & 3;
    const int nk = K >> 5;

    float acc[2][8][4] = {};

    #pragma unroll
    for (int s = 0; s < 2; s++) {
        const int k0 = s * 32;
        #pragma unroll
        for (int i = 0; i < 4; i++) {
            int idx = tid + i * 256, r = idx >> 3, c4 = idx & 7;
            cp16(&As[s][r][c4 * 4], A + (size_t)(m0 + r) * K + k0 + c4 * 4);
        }
        #pragma unroll
        for (int i = 0; i < 4; i++) {
            int idx = tid + i * 256, r = idx >> 3, c4 = idx & 7;
            cp16(&Ws[s][r][c4 * 4], W + (size_t)(n0 + r) * K + k0 + c4 * 4);
        }
        cp_commit();
    }

    for (int kt = 0; kt < nk; kt++) {
        cp_wait1();
        __syncthreads();

        if (kt + 2 < nk) {
            const int sb = (kt + 2) % 3;
            const int k0 = (kt + 2) * 32;
            #pragma unroll
            for (int i = 0; i < 4; i++) {
                int idx = tid + i * 256, r = idx >> 3, c4 = idx & 7;
                cp16(&As[sb][r][c4 * 4], A + (size_t)(m0 + r) * K + k0 + c4 * 4);
            }
            #pragma unroll
            for (int i = 0; i < 4; i++) {
                int idx = tid + i * 256, r = idx >> 3, c4 = idx & 7;
                cp16(&Ws[sb][r][c4 * 4], W + (size_t)(n0 + r) * K + k0 + c4 * 4);
            }
        }
        cp_commit();

        const int buf = kt % 3;
        #pragma unroll
        for (int kk = 0; kk < 4; kk++) {
            const int kb = kk * 8;
            uint32_t a[2][4], b[8][2];
            #pragma unroll
            for (int mi = 0; mi < 2; mi++) {
                int row = wm + mi * 16;
                a[mi][0] = raw(As[buf][row + g][kb + t]);
                a[mi][1] = raw(As[buf][row + 8 + g][kb + t]);
                a[mi][2] = raw(As[buf][row + g][kb + 4 + t]);
                a[mi][3] = raw(As[buf][row + 8 + g][kb + 4 + t]);
            }
            #pragma unroll
            for (int ni = 0; ni < 8; ni++) {
                int col = wn + ni * 8;
                b[ni][0] = raw(Ws[buf][col + g][kb + t]);
                b[ni][1] = raw(Ws[buf][col + g][kb + 4 + t]);
            }
            #pragma unroll
            for (int mi = 0; mi < 2; mi++)
                #pragma unroll
                for (int ni = 0; ni < 8; ni++)
                    mma_tf32(acc[mi][ni], a[mi][0], a[mi][1], a[mi][2], a[mi][3],
                             b[ni][0], b[ni][1]);
        }
    }

    #pragma unroll
    for (int mi = 0; mi < 2; mi++) {
        #pragma unroll
        for (int ni = 0; ni < 8; ni++) {
            int m = m0 + wm + mi * 16 + g;
            int n = n0 + wn + ni * 8 + t * 2;
            float b0 = __ldg(&bias[n]), b1 = __ldg(&bias[n + 1]);
            float v0 = acc[mi][ni][0] + b0;
            float v1 = acc[mi][ni][1] + b1;
            float v2 = acc[mi][ni][2] + b0;
            float v3 = acc[mi][ni][3] + b1;
            if (mode == 0) {
                C[(size_t)m * N + n]           = v0;
                C[(size_t)m * N + n + 1]       = v1;
                C[(size_t)(m + 8) * N + n]     = v2;
                C[(size_t)(m + 8) * N + n + 1] = v3;
            } else if (mode == 2) {
                // transposed sigma store: g_v[(b*EMB + n)*SEQ + sigma_s]
                int bb = m >> 11, s = m & 2047;
                int sp = (s & ~7) | (((s & 3) << 1) | ((s >> 2) & 1));
                C[((size_t)bb * EMB + n) * SEQ + sp]           = rnd(v0);
                C[((size_t)bb * EMB + n + 1) * SEQ + sp]       = rnd(v1);
                C[((size_t)bb * EMB + n) * SEQ + sp + 8]       = rnd(v2);
                C[((size_t)bb * EMB + n + 1) * SEQ + sp + 8]   = rnd(v3);
            } else {
                int nb = n & ~7;
                int p0 = nb + (((n & 3) << 1) | ((n >> 2) & 1));
                int p1 = p0 + 2;
                C[(size_t)m * N + p0]       = rnd(v0);
                C[(size_t)m * N + p1]       = rnd(v1);
                C[(size_t)(m + 8) * N + p0] = rnd(v2);
                C[(size_t)(m + 8) * N + p1] = rnd(v3);
            }
        }
    }
}

// Fused QKV projection.
__global__ __launch_bounds__(256, 2)
void gemm_qkv_tc(const float* __restrict__ A,
                 const float* __restrict__ bq,
                 const float* __restrict__ bk,
                 const float* __restrict__ bv) {
    extern __shared__ __align__(16) float sm[];
    const int z = blockIdx.z;
    const float* W    = (z == 0) ? g_wq : (z == 1) ? g_wk : g_wv;
    const float* bias = (z == 0) ? bq   : (z == 1) ? bk   : bv;
    float* C          = (z == 0) ? g_q  : (z == 1) ? g_k  : g_v;
    const int mode    = (z == 2) ? 2 : 1;
    gemm_body(A, W, bias, C, MTOK, EMB, EMB,
              blockIdx.y * 128, blockIdx.x * 128, mode, sm);
}

// Output projection (plain fp32 store).
__global__ __launch_bounds__(256, 2)
void gemm_out_tc(const float* __restrict__ A,
                 const float* __restrict__ bias,
                 float* __restrict__ C) {
    extern __shared__ __align__(16) float sm[];
    gemm_body(A, g_wo, bias, C, MTOK, EMB, EMB,
              blockIdx.y * 128, blockIdx.x * 128, 0, sm);
}

// ---------------------------------------------------------------------------
// Q a-fragments (sigma-permuted g_q): LDG.64 pairs.
// ---------------------------------------------------------------------------
__device__ __forceinline__ void load_q_frags(uint32_t qa[2][8][4],
                                             int b, int h, int qbase,
                                             int g, int t) {
    #pragma unroll
    for (int mi = 0; mi < 2; mi++) {
        const float* qp = g_q + (size_t)(b * SEQ + qbase + mi * 16) * EMB + h * HDIM;
        #pragma unroll
        for (int d8 = 0; d8 < 8; d8++) {
            int c = d8 * 8 + 2 * t;
            float2 lo = *(const float2*)&qp[(size_t)g * EMB + c];
            float2 hi = *(const float2*)&qp[(size_t)(8 + g) * EMB + c];
            qa[mi][d8][0] = raw(lo.x);
            qa[mi][d8][1] = raw(hi.x);
            qa[mi][d8][2] = raw(lo.y);
            qa[mi][d8][3] = raw(hi.y);
        }
    }
}

// ---------------------------------------------------------------------------
// rowsum: g_inv = 1/rowsum(exp(QK^T*scale)). Q in regs; K smem LDS.64.
// ---------------------------------------------------------------------------
__global__ __launch_bounds__(256, 2)
void rowsum_tc() {
    extern __shared__ __align__(16) float sm[];
    float* Ks = sm;                       // [2][64][KSTR]
    __shared__ float s_red[128];

    const int bh = blockIdx.y;
    const int b  = bh / HEADS;
    const int h  = bh % HEADS;
    const int q0 = blockIdx.x * 128;
    const int tid = threadIdx.x;
    const int wid = tid >> 5;
    const int lane = tid & 31;
    const int wm = (wid >> 1) * 32;
    const int wn = (wid & 1) * 32;
    const int g = lane >> 2;
    const int t = lane & 3;

    if (tid < 128) s_red[tid] = 0.f;

    #pragma unroll
    for (int i = 0; i < 4; i++) {
        int idx = tid + i * 256, r = idx >> 4, c4 = idx & 15;
        cp16(&Ks[r * KSTR + c4 * 4],
             g_k + (size_t)(b * SEQ + r) * EMB + h * HDIM + c4 * 4);
    }
    cp_commit();

    uint32_t qa[2][8][4];
    load_q_frags(qa, b, h, q0 + wm, g, t);

    float rsum[2][2] = {};

    for (int kt = 0; kt < SEQ / 64; kt++) {
        cp_wait0();
        __syncthreads();

        if (kt + 1 < SEQ / 64) {
            float* Kn = Ks + ((kt + 1) & 1) * 64 * KSTR;
            const int r0 = (kt + 1) * 64;
            #pragma unroll
            for (int i = 0; i < 4; i++) {
                int idx = tid + i * 256, r = idx >> 4, c4 = idx & 15;
                cp16(&Kn[r * KSTR + c4 * 4],
                     g_k + (size_t)(b * SEQ + r0 + r) * EMB + h * HDIM + c4 * 4);
            }
            cp_commit();
        }

        const float* Kb = Ks + (kt & 1) * 64 * KSTR;
        float acc[2][4][4] = {};

        #pragma unroll
        for (int d8 = 0; d8 < 8; d8++) {
            const int kb = d8 * 8;
            uint32_t bb[4][2];
            #pragma unroll
            for (int ni = 0; ni < 4; ni++) {
                int col = wn + ni * 8;
                float2 kv = *(const float2*)&Kb[(col + g) * KSTR + kb + 2 * t];
                bb[ni][0] = raw(kv.x);
                bb[ni][1] = raw(kv.y);
            }
            #pragma unroll
            for (int mi = 0; mi < 2; mi++)
                #pragma unroll
                for (int ni = 0; ni < 4; ni++)
                    mma_tf32(acc[mi][ni],
                             qa[mi][d8][0], qa[mi][d8][1], qa[mi][d8][2], qa[mi][d8][3],
                             bb[ni][0], bb[ni][1]);
        }

        #pragma unroll
        for (int mi = 0; mi < 2; mi++)
            #pragma unroll
            for (int ni = 0; ni < 4; ni++) {
                rsum[mi][0] += __expf(acc[mi][ni][0] * SCALE_F)
                             + __expf(acc[mi][ni][1] * SCALE_F);
                rsum[mi][1] += __expf(acc[mi][ni][2] * SCALE_F)
                             + __expf(acc[mi][ni][3] * SCALE_F);
            }
    }

    #pragma unroll
    for (int mi = 0; mi < 2; mi++)
        #pragma unroll
        for (int j = 0; j < 2; j++) {
            rsum[mi][j] += __shfl_xor_sync(0xffffffffu, rsum[mi][j], 1);
            rsum[mi][j] += __shfl_xor_sync(0xffffffffu, rsum[mi][j], 2);
        }

    if (t == 0) {
        #pragma unroll
        for (int mi = 0; mi < 2; mi++) {
            atomicAdd(&s_red[wm + mi * 16 + g],     rsum[mi][0]);
            atomicAdd(&s_red[wm + mi * 16 + 8 + g], rsum[mi][1]);
        }
    }
    __syncthreads();
    if (tid < 128)
        g_inv[(size_t)bh * SEQ + q0 + tid] = 1.0f / s_red[tid];
}

// ---------------------------------------------------------------------------
// flash: scores (Q regs, K LDS.64), p -> gmem from c-frags + frag-major Ps;
// PV a-frags LDS.128, b-frags LDS.64 from transposed V. Per-wm-group named
// barrier for Ps handoff.
// ---------------------------------------------------------------------------
__global__ __launch_bounds__(256, 2)
void flash_pv_tc(float* __restrict__ wbuf) {
    extern __shared__ __align__(16) float sm[];
    float* Ks = sm;                               // [2][64][KSTR]
    float* Vs = Ks + 2 * 64 * KSTR;               // [2][64 d][VSTR s]
    float* Ps = Vs + 2 * 64 * VSTR;               // [32][PSBLK]

    const int bh = blockIdx.y;
    const int b  = bh / HEADS;
    const int h  = bh % HEADS;
    const int q0 = blockIdx.x * 64;
    const int tid = threadIdx.x;
    const int wid = tid >> 5;
    const int lane = tid & 31;
    const int wm = (wid >> 2) * 32;
    const int wn = (wid & 3) * 16;
    const int g = lane >> 2;
    const int t = lane & 3;
    const int grp_bar = 1 + (wid >> 2);           // named barrier per wm group

    // V^T gmem base for this (b,h): rows = d (64), cols = s
    const float* vt = g_v + ((size_t)b * EMB + h * HDIM) * SEQ;

    #pragma unroll
    for (int i = 0; i < 4; i++) {
        int idx = tid + i * 256, r = idx >> 4, c4 = idx & 15;
        cp16(&Ks[r * KSTR + c4 * 4],
             g_k + (size_t)(b * SEQ + r) * EMB + h * HDIM + c4 * 4);
        cp16(&Vs[r * VSTR + c4 * 4], vt + (size_t)r * SEQ + c4 * 4);
    }
    cp_commit();

    uint32_t qa[2][8][4];
    load_q_frags(qa, b, h, q0 + wm, g, t);

    float iv[2][2];
    #pragma unroll
    for (int mi = 0; mi < 2; mi++) {
        iv[mi][0] = g_inv[(size_t)bh * SEQ + q0 + wm + mi * 16 + g];
        iv[mi][1] = g_inv[(size_t)bh * SEQ + q0 + wm + mi * 16 + 8 + g];
    }

    float* prow = wbuf + (size_t)bh * SEQ * SEQ;
    float acc_o[2][2][4] = {};

    const int tp0 = (2 * t) & 3;
    const int tp1 = (2 * t + 1) & 3;
    const int j0  = 2 * (t >> 1);

    for (int kt = 0; kt < SEQ / 64; kt++) {
        cp_wait0();
        __syncthreads();

        if (kt + 1 < SEQ / 64) {
            const int nb = (kt + 1) & 1;
            const int r0 = (kt + 1) * 64;
            float* Kn = Ks + nb * 64 * KSTR;
            float* Vn = Vs + nb * 64 * VSTR;
            #pragma unroll
            for (int i = 0; i < 4; i++) {
                int idx = tid + i * 256, r = idx >> 4, c4 = idx & 15;
                cp16(&Kn[r * KSTR + c4 * 4],
                     g_k + (size_t)(b * SEQ + r0 + r) * EMB + h * HDIM + c4 * 4);
                cp16(&Vn[r * VSTR + c4 * 4], vt + (size_t)r * SEQ + r0 + c4 * 4);
            }
            cp_commit();
        }

        const float* Kb = Ks + (kt & 1) * 64 * KSTR;
        const float* Vb = Vs + (kt & 1) * 64 * VSTR;

        float acc_s[2][2][4] = {};
        #pragma unroll
        for (int d8 = 0; d8 < 8; d8++) {
            const int kb = d8 * 8;
            uint32_t bb[2][2];
            #pragma unroll
            for (int ni = 0; ni < 2; ni++) {
                int col = wn + ni * 8;
                float2 kv = *(const float2*)&Kb[(col + g) * KSTR + kb + 2 * t];
                bb[ni][0] = raw(kv.x);
                bb[ni][1] = raw(kv.y);
            }
            #pragma unroll
            for (int mi = 0; mi < 2; mi++)
                #pragma unroll
                for (int ni = 0; ni < 2; ni++)
                    mma_tf32(acc_s[mi][ni],
                             qa[mi][d8][0], qa[mi][d8][1], qa[mi][d8][2], qa[mi][d8][3],
                             bb[ni][0], bb[ni][1]);
        }

        #pragma unroll
        for (int mi = 0; mi < 2; mi++) {
            const int mt = (wm >> 4) + mi;
            const int r0g = q0 + wm + mi * 16 + g;
            #pragma unroll
            for (int ni = 0; ni < 2; ni++) {
                const int c0 = wn + ni * 8 + 2 * t;
                const int chunk = (wn >> 3) + ni;
                float p00 = rnd(__expf(acc_s[mi][ni][0] * SCALE_F) * iv[mi][0]);
                float p01 = rnd(__expf(acc_s[mi][ni][1] * SCALE_F) * iv[mi][0]);
                float p10 = rnd(__expf(acc_s[mi][ni][2] * SCALE_F) * iv[mi][1]);
                float p11 = rnd(__expf(acc_s[mi][ni][3] * SCALE_F) * iv[mi][1]);
                *(float2*)&prow[(size_t)r0g * SEQ + kt * 64 + c0]       = make_float2(p00, p01);
                *(float2*)&prow[(size_t)(r0g + 8) * SEQ + kt * 64 + c0] = make_float2(p10, p11);
                float* pb = &Ps[(mt * 8 + chunk) * PSBLK];
                *(float2*)&pb[(g * 4 + tp0) * 4 + j0] = make_float2(p00, p10);
                *(float2*)&pb[(g * 4 + tp1) * 4 + j0] = make_float2(p01, p11);
            }
        }
        // Ps handoff only involves the 4 wn-warps of this wm group
        asm volatile("bar.sync %0, 128;" :: "r"(grp_bar) : "memory");

        #pragma unroll
        for (int d8 = 0; d8 < 8; d8++) {
            const int kb = d8 * 8;
            uint32_t a[2][4];
            #pragma unroll
            for (int mi = 0; mi < 2; mi++) {
                const int mt = (wm >> 4) + mi;
                float4 av = *(const float4*)&Ps[(mt * 8 + d8) * PSBLK + lane * 4];
                a[mi][0] = raw(av.x);
                a[mi][1] = raw(av.y);
                a[mi][2] = raw(av.z);
                a[mi][3] = raw(av.w);
            }
            uint32_t bb[2][2];
            #pragma unroll
            for (int ni = 0; ni < 2; ni++) {
                int col = wn + ni * 8;
                // V^T: row = d (col+g), cols = sigma'd s chunk -> LDS.64
                float2 vv = *(const float2*)&Vb[(col + g) * VSTR + kb + 2 * t];
                bb[ni][0] = raw(vv.x);
                bb[ni][1] = raw(vv.y);
            }
            #pragma unroll
            for (int mi = 0; mi < 2; mi++)
                #pragma unroll
                for (int ni = 0; ni < 2; ni++)
                    mma_tf32(acc_o[mi][ni], a[mi][0], a[mi][1], a[mi][2], a[mi][3],
                             bb[ni][0], bb[ni][1]);
        }
    }

    #pragma unroll
    for (int mi = 0; mi < 2; mi++) {
        #pragma unroll
        for (int ni = 0; ni < 2; ni++) {
            int m = q0 + wm + mi * 16 + g;
            int d = wn + ni * 8 + t * 2;
            g_att[(size_t)(b * SEQ + m) * EMB + h * HDIM + d]         = rnd(acc_o[mi][ni][0]);
            g_att[(size_t)(b * SEQ + m) * EMB + h * HDIM + d + 1]     = rnd(acc_o[mi][ni][1]);
            g_att[(size_t)(b * SEQ + m + 8) * EMB + h * HDIM + d]     = rnd(acc_o[mi][ni][2]);
            g_att[(size_t)(b * SEQ + m + 8) * EMB + h * HDIM + d + 1] = rnd(acc_o[mi][ni][3]);
        }
    }
}

// ---------------------------------------------------------------------------
// launch
// ---------------------------------------------------------------------------
extern "C" void kernel_launch(void* const* d_in, const int* in_sizes, int n_in,
                              void* d_out, int out_size) {
    (void)in_sizes; (void)n_in; (void)out_size;

    const float* hs = (const float*)d_in[0];
    const float* Wq = (const float*)d_in[1];
    const float* bq = (const float*)d_in[2];
    const float* Wk = (const float*)d_in[3];
    const float* bk = (const float*)d_in[4];
    const float* Wv = (const float*)d_in[5];
    const float* bv = (const float*)d_in[6];
    const float* Wo = (const float*)d_in[7];
    const float* bo = (const float*)d_in[8];

    float* out      = (float*)d_out;
    float* attn_out = out;
    float* wbuf     = out + (size_t)MTOK * EMB;

    float* datt, * dhsr, * dwq, * dwk, * dwv, * dwo;
    cudaGetSymbolAddress((void**)&datt, g_att);
    cudaGetSymbolAddress((void**)&dhsr, g_hsr);
    cudaGetSymbolAddress((void**)&dwq,  g_wq);
    cudaGetSymbolAddress((void**)&dwk,  g_wk);
    cudaGetSymbolAddress((void**)&dwv,  g_wv);
    cudaGetSymbolAddress((void**)&dwo,  g_wo);

    const int smem_gemm  = (3 * 128 * PAD + 3 * 128 * PAD) * 4;                 // 110592
    const int smem_rsum  = (2 * 64 * KSTR) * 4;                                 // 36864
    const int smem_flash = (2 * 64 * KSTR + 2 * 64 * VSTR + 32 * PSBLK) * 4;    // 90624

    cudaFuncSetAttribute(gemm_qkv_tc, cudaFuncAttributeMaxDynamicSharedMemorySize, smem_gemm);
    cudaFuncSetAttribute(gemm_out_tc, cudaFuncAttributeMaxDynamicSharedMemorySize, smem_gemm);
    cudaFuncSetAttribute(rowsum_tc,   cudaFuncAttributeMaxDynamicSharedMemorySize, smem_rsum);
    cudaFuncSetAttribute(flash_pv_tc, cudaFuncAttributeMaxDynamicSharedMemorySize, smem_flash);

    // fused pre-round (hs + 4 weights), one launch
    const int n4_hs = MTOK * EMB / 4;
    const int n4_w  = EMB * EMB / 4;
    const int n4_total = n4_hs + 4 * n4_w;
    round_all_kernel<<<(n4_total + 255) / 256, 256>>>(
        (const float4*)hs, (const float4*)Wq, (const float4*)Wk,
        (const float4*)Wv, (const float4*)Wo,
        (float4*)dhsr, (float4*)dwq, (float4*)dwk, (float4*)dwv, (float4*)dwo,
        n4_hs, n4_w);

    // fused QKV projections: one launch, grid.z = 3
    gemm_qkv_tc<<<dim3(EMB / 128, MTOK / 128, 3), 256, smem_gemm>>>(dhsr, bq, bk, bv);

    rowsum_tc<<<dim3(SEQ / 128, BH), 256, smem_rsum>>>();

    flash_pv_tc<<<dim3(SEQ / 64, BH), 256, smem_flash>>>(wbuf);

    gemm_out_tc<<<dim3(EMB / 128, MTOK / 128), 256, smem_gemm>>>(datt, bo, attn_out);
}

// round 15
// speedup vs baseline: 1.0161x; 1.0161x over previous
#include <cuda_runtime.h>
#include <cuda_bf16.h>
#include <math.h>
#include <stdint.h>

// ---------------------------------------------------------------------------
// ViT attention: TF32 mma.sync, pre-rounded tf32 operands, PI-permuted
// (quad-fragment) Q/K head-dim layouts and transposed V (all attention
// b-fragment loads are single conflict-free LDS.128), fragment-major P
// staging, single-sync cp.async pipelines, fused launches.
// B=4, S=2048, E=768, H=12, D=64.
// d_out = attn_output [4,2048,768] ++ attn_weights [4,12,2048,2048].
//
// pi (within each 16-group of a contraction dim): pos(d) = 4*(d&3) + (d>>2).
// Thread t's float4 at [16*g16 + 4t] = logical {t, 4+t, 8+t, 12+t} = the
// b-fragments of mma chunks 2*g16 and 2*g16+1.
// ---------------------------------------------------------------------------

#define BATCH     4
#define SEQ       2048
#define EMB       768
#define HEADS     12
#define HDIM      64
#define MTOK      (BATCH * SEQ)
#define BH        (BATCH * HEADS)
#define SCALE_F   0.125f

#define PAD       36      // projection smem stride (LDS.32 conflict-free)
#define KSTR      80      // K tile stride: 80 % 32 == 16 -> LDS.128 conflict-free
#define VSTR      80      // V^T tile stride
#define PSBLK     132     // Ps words per (mt,chunk) block

// Scratch (device globals). All tf32-rounded.
// g_q/g_k pi-permuted along d. g_v TRANSPOSED [B][EMB][SEQ], s pi-permuted.
__device__ float g_q[MTOK * EMB];
__device__ float g_k[MTOK * EMB];
__device__ float g_v[MTOK * EMB];
__device__ float g_att[MTOK * EMB];
__device__ float g_inv[BH * SEQ];
__device__ float g_hsr[MTOK * EMB];
__device__ float g_wq[EMB * EMB];
__device__ float g_wk[EMB * EMB];
__device__ float g_wv[EMB * EMB];
__device__ float g_wo[EMB * EMB];

// ---------------------------------------------------------------------------
__device__ __forceinline__ void cp16(void* s, const void* g) {
    uint32_t sa = (uint32_t)__cvta_generic_to_shared(s);
    asm volatile("cp.async.cg.shared.global [%0], [%1], 16;\n" :: "r"(sa), "l"(g));
}
__device__ __forceinline__ void cp_commit() {
    asm volatile("cp.async.commit_group;\n" ::: "memory");
}
__device__ __forceinline__ void cp_wait1() {
    asm volatile("cp.async.wait_group 1;\n" ::: "memory");
}
__device__ __forceinline__ void cp_wait0() {
    asm volatile("cp.async.wait_group 0;\n" ::: "memory");
}

__device__ __forceinline__ float rnd(float x) {
    float r;
    asm("cvt.rna.tf32.f32 %0, %1;" : "=f"(r) : "f"(x));
    return r;
}
__device__ __forceinline__ uint32_t raw(float x) { return __float_as_uint(x); }

__device__ __forceinline__ void mma_tf32(float c[4],
                                         uint32_t a0, uint32_t a1, uint32_t a2, uint32_t a3,
                                         uint32_t b0, uint32_t b1) {
    asm volatile(
        "mma.sync.aligned.m16n8k8.row.col.f32.tf32.tf32.f32 "
        "{%0,%1,%2,%3}, {%4,%5,%6,%7}, {%8,%9}, {%0,%1,%2,%3};\n"
        : "+f"(c[0]), "+f"(c[1]), "+f"(c[2]), "+f"(c[3])
        : "r"(a0), "r"(a1), "r"(a2), "r"(a3), "r"(b0), "r"(b1));
}

// ---------------------------------------------------------------------------
// Fused pre-round: hs + 4 weight matrices, one launch (plain rounding).
// ---------------------------------------------------------------------------
__global__ void round_all_kernel(const float4* __restrict__ hs,
                                 const float4* __restrict__ wq,
                                 const float4* __restrict__ wk,
                                 const float4* __restrict__ wv,
                                 const float4* __restrict__ wo,
                                 float4* __restrict__ dhsr,
                                 float4* __restrict__ dwq,
                                 float4* __restrict__ dwk,
                                 float4* __restrict__ dwv,
                                 float4* __restrict__ dwo,
                                 int n4_hs, int n4_w) {
    int i = blockIdx.x * blockDim.x + threadIdx.x;
    const float4* in;
    float4* out;
    int j = i;
    if (j < n4_hs)            { in = hs; out = dhsr; }
    else if ((j -= n4_hs) < n4_w)  { in = wq; out = dwq; }
    else if ((j -= n4_w) < n4_w)   { in = wk; out = dwk; }
    else if ((j -= n4_w) < n4_w)   { in = wv; out = dwv; }
    else if ((j -= n4_w) < n4_w)   { in = wo; out = dwo; }
    else return;
    float4 v = in[j];
    v.x = rnd(v.x); v.y = rnd(v.y); v.z = rnd(v.z); v.w = rnd(v.w);
    out[j] = v;
}

// ---------------------------------------------------------------------------
// Shared GEMM mainloop body (unchanged hot loop; LDS.32 conflict-free).
// Epilogue mode: 0 plain fp32; 1 rounded + pi(n) (g_q/g_k);
//                2 rounded TRANSPOSED + pi(s) (g_v as [B][E][S]).
// ---------------------------------------------------------------------------
__device__ __forceinline__ void gemm_body(const float* __restrict__ A,
                                          const float* __restrict__ W,
                                          const float* __restrict__ bias,
                                          float* __restrict__ C,
                                          int M, int N, int K,
                                          int m0, int n0, int mode,
                                          float* sm) {
    float (*As)[128][PAD] = (float (*)[128][PAD])sm;
    float (*Ws)[128][PAD] = (float (*)[128][PAD])(sm + 3 * 128 * PAD);

    const int tid = threadIdx.x;
    const int wid = tid >> 5;
    const int lane = tid & 31;
    const int wm = (wid >> 1) * 32;
    const int wn = (wid & 1) * 64;
    const int g = lane >> 2;
    const int t = lane & 3;
    const int nk = K >> 5;

    float acc[2][8][4] = {};

    #pragma unroll
    for (int s = 0; s < 2; s++) {
        const int k0 = s * 32;
        #pragma unroll
        for (int i = 0; i < 4; i++) {
            int idx = tid + i * 256, r = idx >> 3, c4 = idx & 7;
            cp16(&As[s][r][c4 * 4], A + (size_t)(m0 + r) * K + k0 + c4 * 4);
        }
        #pragma unroll
        for (int i = 0; i < 4; i++) {
            int idx = tid + i * 256, r = idx >> 3, c4 = idx & 7;
            cp16(&Ws[s][r][c4 * 4], W + (size_t)(n0 + r) * K + k0 + c4 * 4);
        }
        cp_commit();
    }

    for (int kt = 0; kt < nk; kt++) {
        cp_wait1();
        __syncthreads();

        if (kt + 2 < nk) {
            const int sb = (kt + 2) % 3;
            const int k0 = (kt + 2) * 32;
            #pragma unroll
            for (int i = 0; i < 4; i++) {
                int idx = tid + i * 256, r = idx >> 3, c4 = idx & 7;
                cp16(&As[sb][r][c4 * 4], A + (size_t)(m0 + r) * K + k0 + c4 * 4);
            }
            #pragma unroll
            for (int i = 0; i < 4; i++) {
                int idx = tid + i * 256, r = idx >> 3, c4 = idx & 7;
                cp16(&Ws[sb][r][c4 * 4], W + (size_t)(n0 + r) * K + k0 + c4 * 4);
            }
        }
        cp_commit();

        const int buf = kt % 3;
        #pragma unroll
        for (int kk = 0; kk < 4; kk++) {
            const int kb = kk * 8;
            uint32_t a[2][4], b[8][2];
            #pragma unroll
            for (int mi = 0; mi < 2; mi++) {
                int row = wm + mi * 16;
                a[mi][0] = raw(As[buf][row + g][kb + t]);
                a[mi][1] = raw(As[buf][row + 8 + g][kb + t]);
                a[mi][2] = raw(As[buf][row + g][kb + 4 + t]);
                a[mi][3] = raw(As[buf][row + 8 + g][kb + 4 + t]);
            }
            #pragma unroll
            for (int ni = 0; ni < 8; ni++) {
                int col = wn + ni * 8;
                b[ni][0] = raw(Ws[buf][col + g][kb + t]);
                b[ni][1] = raw(Ws[buf][col + g][kb + 4 + t]);
            }
            #pragma unroll
            for (int mi = 0; mi < 2; mi++)
                #pragma unroll
                for (int ni = 0; ni < 8; ni++)
                    mma_tf32(acc[mi][ni], a[mi][0], a[mi][1], a[mi][2], a[mi][3],
                             b[ni][0], b[ni][1]);
        }
    }

    #pragma unroll
    for (int mi = 0; mi < 2; mi++) {
        #pragma unroll
        for (int ni = 0; ni < 8; ni++) {
            int m = m0 + wm + mi * 16 + g;
            int n = n0 + wn + ni * 8 + t * 2;     // even
            float b0 = __ldg(&bias[n]), b1 = __ldg(&bias[n + 1]);
            float v0 = acc[mi][ni][0] + b0;
            float v1 = acc[mi][ni][1] + b1;
            float v2 = acc[mi][ni][2] + b0;
            float v3 = acc[mi][ni][3] + b1;
            if (mode == 0) {
                C[(size_t)m * N + n]           = v0;
                C[(size_t)m * N + n + 1]       = v1;
                C[(size_t)(m + 8) * N + n]     = v2;
                C[(size_t)(m + 8) * N + n + 1] = v3;
            } else if (mode == 2) {
                // V^T with pi(s): g_v[(b*EMB + n)*SEQ + pi_s]
                int bb = m >> 11, s = m & 2047;
                int sp = (s & ~15) + 4 * (s & 3) + ((s >> 2) & 3);
                // rows m and m+8: pi(s+8) = pi(s) + 2
                C[((size_t)bb * EMB + n) * SEQ + sp]         = rnd(v0);
                C[((size_t)bb * EMB + n + 1) * SEQ + sp]     = rnd(v1);
                C[((size_t)bb * EMB + n) * SEQ + sp + 2]     = rnd(v2);
                C[((size_t)bb * EMB + n + 1) * SEQ + sp + 2] = rnd(v3);
            } else {
                // pi(n): n even -> pi(n+1) = pi(n) + 4
                int p0 = (n & ~15) + 4 * (n & 3) + ((n >> 2) & 3);
                int p1 = p0 + 4;
                C[(size_t)m * N + p0]       = rnd(v0);
                C[(size_t)m * N + p1]       = rnd(v1);
                C[(size_t)(m + 8) * N + p0] = rnd(v2);
                C[(size_t)(m + 8) * N + p1] = rnd(v3);
            }
        }
    }
}

// Fused QKV projection.
__global__ __launch_bounds__(256, 2)
void gemm_qkv_tc(const float* __restrict__ A,
                 const float* __restrict__ bq,
                 const float* __restrict__ bk,
                 const float* __restrict__ bv) {
    extern __shared__ __align__(16) float sm[];
    const int z = blockIdx.z;
    const float* W    = (z == 0) ? g_wq : (z == 1) ? g_wk : g_wv;
    const float* bias = (z == 0) ? bq   : (z == 1) ? bk   : bv;
    float* C          = (z == 0) ? g_q  : (z == 1) ? g_k  : g_v;
    const int mode    = (z == 2) ? 2 : 1;
    gemm_body(A, W, bias, C, MTOK, EMB, EMB,
              blockIdx.y * 128, blockIdx.x * 128, mode, sm);
}

// Output projection (plain fp32 store).
__global__ __launch_bounds__(256, 2)
void gemm_out_tc(const float* __restrict__ A,
                 const float* __restrict__ bias,
                 float* __restrict__ C) {
    extern __shared__ __align__(16) float sm[];
    gemm_body(A, g_wo, bias, C, MTOK, EMB, EMB,
              blockIdx.y * 128, blockIdx.x * 128, 0, sm);
}

// ---------------------------------------------------------------------------
// Q a-fragments (pi-permuted g_q): LDG.128 pairs. qa[mi][d8] for d8 = 0..7.
// ---------------------------------------------------------------------------
__device__ __forceinline__ void load_q_frags(uint32_t qa[2][8][4],
                                             int b, int h, int qbase,
                                             int g, int t) {
    #pragma unroll
    for (int mi = 0; mi < 2; mi++) {
        const float* qp = g_q + (size_t)(b * SEQ + qbase + mi * 16) * EMB + h * HDIM;
        #pragma unroll
        for (int g16 = 0; g16 < 4; g16++) {
            int c = g16 * 16 + 4 * t;
            float4 lo = *(const float4*)&qp[(size_t)g * EMB + c];
            float4 hi = *(const float4*)&qp[(size_t)(8 + g) * EMB + c];
            qa[mi][2 * g16][0]     = raw(lo.x);   // k=t
            qa[mi][2 * g16][1]     = raw(hi.x);
            qa[mi][2 * g16][2]     = raw(lo.y);   // k=4+t
            qa[mi][2 * g16][3]     = raw(hi.y);
            qa[mi][2 * g16 + 1][0] = raw(lo.z);   // k=8+t
            qa[mi][2 * g16 + 1][1] = raw(hi.z);
            qa[mi][2 * g16 + 1][2] = raw(lo.w);   // k=12+t
            qa[mi][2 * g16 + 1][3] = raw(hi.w);
        }
    }
}

// ---------------------------------------------------------------------------
// rowsum: g_inv = 1/rowsum(exp(QK^T*scale)). Q in regs; K b-frags LDS.128.
// grid (SEQ/128, BH), 8 warps 4m x 2n.
// ---------------------------------------------------------------------------
__global__ __launch_bounds__(256, 2)
void rowsum_tc() {
    extern __shared__ __align__(16) float sm[];
    float* Ks = sm;                       // [2][64][KSTR]
    __shared__ float s_red[128];

    const int bh = blockIdx.y;
    const int b  = bh / HEADS;
    const int h  = bh % HEADS;
    const int q0 = blockIdx.x * 128;
    const int tid = threadIdx.x;
    const int wid = tid >> 5;
    const int lane = tid & 31;
    const int wm = (wid >> 1) * 32;
    const int wn = (wid & 1) * 32;
    const int g = lane >> 2;
    const int t = lane & 3;

    if (tid < 128) s_red[tid] = 0.f;

    #pragma unroll
    for (int i = 0; i < 4; i++) {
        int idx = tid + i * 256, r = idx >> 4, c4 = idx & 15;
        cp16(&Ks[r * KSTR + c4 * 4],
             g_k + (size_t)(b * SEQ + r) * EMB + h * HDIM + c4 * 4);
    }
    cp_commit();

    uint32_t qa[2][8][4];
    load_q_frags(qa, b, h, q0 + wm, g, t);

    float rsum[2][2] = {};

    for (int kt = 0; kt < SEQ / 64; kt++) {
        cp_wait0();
        __syncthreads();

        if (kt + 1 < SEQ / 64) {
            float* Kn = Ks + ((kt + 1) & 1) * 64 * KSTR;
            const int r0 = (kt + 1) * 64;
            #pragma unroll
            for (int i = 0; i < 4; i++) {
                int idx = tid + i * 256, r = idx >> 4, c4 = idx & 15;
                cp16(&Kn[r * KSTR + c4 * 4],
                     g_k + (size_t)(b * SEQ + r0 + r) * EMB + h * HDIM + c4 * 4);
            }
            cp_commit();
        }

        const float* Kb = Ks + (kt & 1) * 64 * KSTR;
        float acc[2][4][4] = {};

        #pragma unroll
        for (int g16 = 0; g16 < 4; g16++) {
            float4 kv[4];
            #pragma unroll
            for (int ni = 0; ni < 4; ni++) {
                int col = wn + ni * 8;
                kv[ni] = *(const float4*)&Kb[(col + g) * KSTR + g16 * 16 + 4 * t];
            }
            #pragma unroll
            for (int sub = 0; sub < 2; sub++) {
                const int d8 = 2 * g16 + sub;
                #pragma unroll
                for (int mi = 0; mi < 2; mi++)
                    #pragma unroll
                    for (int ni = 0; ni < 4; ni++) {
                        uint32_t b0 = raw(sub ? kv[ni].z : kv[ni].x);
                        uint32_t b1 = raw(sub ? kv[ni].w : kv[ni].y);
                        mma_tf32(acc[mi][ni],
                                 qa[mi][d8][0], qa[mi][d8][1], qa[mi][d8][2], qa[mi][d8][3],
                                 b0, b1);
                    }
            }
        }

        #pragma unroll
        for (int mi = 0; mi < 2; mi++)
            #pragma unroll
            for (int ni = 0; ni < 4; ni++) {
                rsum[mi][0] += __expf(acc[mi][ni][0] * SCALE_F)
                             + __expf(acc[mi][ni][1] * SCALE_F);
                rsum[mi][1] += __expf(acc[mi][ni][2] * SCALE_F)
                             + __expf(acc[mi][ni][3] * SCALE_F);
            }
    }

    #pragma unroll
    for (int mi = 0; mi < 2; mi++)
        #pragma unroll
        for (int j = 0; j < 2; j++) {
            rsum[mi][j] += __shfl_xor_sync(0xffffffffu, rsum[mi][j], 1);
            rsum[mi][j] += __shfl_xor_sync(0xffffffffu, rsum[mi][j], 2);
        }

    if (t == 0) {
        #pragma unroll
        for (int mi = 0; mi < 2; mi++) {
            atomicAdd(&s_red[wm + mi * 16 + g],     rsum[mi][0]);
            atomicAdd(&s_red[wm + mi * 16 + 8 + g], rsum[mi][1]);
        }
    }
    __syncthreads();
    if (tid < 128)
        g_inv[(size_t)bh * SEQ + q0 + tid] = 1.0f / s_red[tid];
}

// ---------------------------------------------------------------------------
// flash: scores (Q regs, K LDS.128), p -> gmem from c-frags + frag-major Ps;
// PV a-frags LDS.128, b-frags LDS.128 from pi-permuted V^T. Per-wm-group
// named barrier for Ps handoff.
// ---------------------------------------------------------------------------
__global__ __launch_bounds__(256, 2)
void flash_pv_tc(float* __restrict__ wbuf) {
    extern __shared__ __align__(16) float sm[];
    float* Ks = sm;                               // [2][64][KSTR]
    float* Vs = Ks + 2 * 64 * KSTR;               // [2][64 d][VSTR s]
    float* Ps = Vs + 2 * 64 * VSTR;               // [32][PSBLK]

    const int bh = blockIdx.y;
    const int b  = bh / HEADS;
    const int h  = bh % HEADS;
    const int q0 = blockIdx.x * 64;
    const int tid = threadIdx.x;
    const int wid = tid >> 5;
    const int lane = tid & 31;
    const int wm = (wid >> 2) * 32;
    const int wn = (wid & 3) * 16;
    const int g = lane >> 2;
    const int t = lane & 3;
    const int grp_bar = 1 + (wid >> 2);

    const float* vt = g_v + ((size_t)b * EMB + h * HDIM) * SEQ;

    #pragma unroll
    for (int i = 0; i < 4; i++) {
        int idx = tid + i * 256, r = idx >> 4, c4 = idx & 15;
        cp16(&Ks[r * KSTR + c4 * 4],
             g_k + (size_t)(b * SEQ + r) * EMB + h * HDIM + c4 * 4);
        cp16(&Vs[r * VSTR + c4 * 4], vt + (size_t)r * SEQ + c4 * 4);
    }
    cp_commit();

    uint32_t qa[2][8][4];
    load_q_frags(qa, b, h, q0 + wm, g, t);

    float iv[2][2];
    #pragma unroll
    for (int mi = 0; mi < 2; mi++) {
        iv[mi][0] = g_inv[(size_t)bh * SEQ + q0 + wm + mi * 16 + g];
        iv[mi][1] = g_inv[(size_t)bh * SEQ + q0 + wm + mi * 16 + 8 + g];
    }

    float* prow = wbuf + (size_t)bh * SEQ * SEQ;
    float acc_o[2][2][4] = {};

    const int tp0 = (2 * t) & 3;
    const int tp1 = (2 * t + 1) & 3;
    const int j0  = 2 * (t >> 1);

    for (int kt = 0; kt < SEQ / 64; kt++) {
        cp_wait0();
        __syncthreads();

        if (kt + 1 < SEQ / 64) {
            const int nb = (kt + 1) & 1;
            const int r0 = (kt + 1) * 64;
            float* Kn = Ks + nb * 64 * KSTR;
            float* Vn = Vs + nb * 64 * VSTR;
            #pragma unroll
            for (int i = 0; i < 4; i++) {
                int idx = tid + i * 256, r = idx >> 4, c4 = idx & 15;
                cp16(&Kn[r * KSTR + c4 * 4],
                     g_k + (size_t)(b * SEQ + r0 + r) * EMB + h * HDIM + c4 * 4);
                cp16(&Vn[r * VSTR + c4 * 4], vt + (size_t)r * SEQ + r0 + c4 * 4);
            }
            cp_commit();
        }

        const float* Kb = Ks + (kt & 1) * 64 * KSTR;
        const float* Vb = Vs + (kt & 1) * 64 * VSTR;

        // scores: b-frags via LDS.128 (two chunks per load)
        float acc_s[2][2][4] = {};
        #pragma unroll
        for (int g16 = 0; g16 < 4; g16++) {
            float4 kv[2];
            #pragma unroll
            for (int ni = 0; ni < 2; ni++) {
                int col = wn + ni * 8;
                kv[ni] = *(const float4*)&Kb[(col + g) * KSTR + g16 * 16 + 4 * t];
            }
            #pragma unroll
            for (int sub = 0; sub < 2; sub++) {
                const int d8 = 2 * g16 + sub;
                #pragma unroll
                for (int mi = 0; mi < 2; mi++)
                    #pragma unroll
                    for (int ni = 0; ni < 2; ni++) {
                        uint32_t b0 = raw(sub ? kv[ni].z : kv[ni].x);
                        uint32_t b1 = raw(sub ? kv[ni].w : kv[ni].y);
                        mma_tf32(acc_s[mi][ni],
                                 qa[mi][d8][0], qa[mi][d8][1], qa[mi][d8][2], qa[mi][d8][3],
                                 b0, b1);
                    }
            }
        }

        // p = exp(s)*inv -> gmem (c-frag direct) + Ps (frag-major)
        #pragma unroll
        for (int mi = 0; mi < 2; mi++) {
            const int mt = (wm >> 4) + mi;
            const int r0g = q0 + wm + mi * 16 + g;
            #pragma unroll
            for (int ni = 0; ni < 2; ni++) {
                const int c0 = wn + ni * 8 + 2 * t;
                const int chunk = (wn >> 3) + ni;
                float p00 = rnd(__expf(acc_s[mi][ni][0] * SCALE_F) * iv[mi][0]);
                float p01 = rnd(__expf(acc_s[mi][ni][1] * SCALE_F) * iv[mi][0]);
                float p10 = rnd(__expf(acc_s[mi][ni][2] * SCALE_F) * iv[mi][1]);
                float p11 = rnd(__expf(acc_s[mi][ni][3] * SCALE_F) * iv[mi][1]);
                *(float2*)&prow[(size_t)r0g * SEQ + kt * 64 + c0]       = make_float2(p00, p01);
                *(float2*)&prow[(size_t)(r0g + 8) * SEQ + kt * 64 + c0] = make_float2(p10, p11);
                float* pb = &Ps[(mt * 8 + chunk) * PSBLK];
                *(float2*)&pb[(g * 4 + tp0) * 4 + j0] = make_float2(p00, p10);
                *(float2*)&pb[(g * 4 + tp1) * 4 + j0] = make_float2(p01, p11);
            }
        }
        asm volatile("bar.sync %0, 128;" :: "r"(grp_bar) : "memory");

        // O += p @ V : a LDS.128 from Ps; b LDS.128 from pi'd V^T
        #pragma unroll
        for (int s16 = 0; s16 < 4; s16++) {
            float4 vv[2];
            #pragma unroll
            for (int ni = 0; ni < 2; ni++) {
                int col = wn + ni * 8;
                vv[ni] = *(const float4*)&Vb[(col + g) * VSTR + s16 * 16 + 4 * t];
            }
            #pragma unroll
            for (int sub = 0; sub < 2; sub++) {
                const int d8 = 2 * s16 + sub;
                uint32_t a[2][4];
                #pragma unroll
                for (int mi = 0; mi < 2; mi++) {
                    const int mt = (wm >> 4) + mi;
                    float4 av = *(const float4*)&Ps[(mt * 8 + d8) * PSBLK + lane * 4];
                    a[mi][0] = raw(av.x);
                    a[mi][1] = raw(av.y);
                    a[mi][2] = raw(av.z);
                    a[mi][3] = raw(av.w);
                }
                #pragma unroll
                for (int mi = 0; mi < 2; mi++)
                    #pragma unroll
                    for (int ni = 0; ni < 2; ni++) {
                        uint32_t b0 = raw(sub ? vv[ni].z : vv[ni].x);
                        uint32_t b1 = raw(sub ? vv[ni].w : vv[ni].y);
                        mma_tf32(acc_o[mi][ni], a[mi][0], a[mi][1], a[mi][2], a[mi][3],
                                 b0, b1);
                    }
            }
        }
    }

    #pragma unroll
    for (int mi = 0; mi < 2; mi++) {
        #pragma unroll
        for (int ni = 0; ni < 2; ni++) {
            int m = q0 + wm + mi * 16 + g;
            int d = wn + ni * 8 + t * 2;
            g_att[(size_t)(b * SEQ + m) * EMB + h * HDIM + d]         = rnd(acc_o[mi][ni][0]);
            g_att[(size_t)(b * SEQ + m) * EMB + h * HDIM + d + 1]     = rnd(acc_o[mi][ni][1]);
            g_att[(size_t)(b * SEQ + m + 8) * EMB + h * HDIM + d]     = rnd(acc_o[mi][ni][2]);
            g_att[(size_t)(b * SEQ + m + 8) * EMB + h * HDIM + d + 1] = rnd(acc_o[mi][ni][3]);
        }
    }
}

// ---------------------------------------------------------------------------
// launch
// ---------------------------------------------------------------------------
extern "C" void kernel_launch(void* const* d_in, const int* in_sizes, int n_in,
                              void* d_out, int out_size) {
    (void)in_sizes; (void)n_in; (void)out_size;

    const float* hs = (const float*)d_in[0];
    const float* Wq = (const float*)d_in[1];
    const float* bq = (const float*)d_in[2];
    const float* Wk = (const float*)d_in[3];
    const float* bk = (const float*)d_in[4];
    const float* Wv = (const float*)d_in[5];
    const float* bv = (const float*)d_in[6];
    const float* Wo = (const float*)d_in[7];
    const float* bo = (const float*)d_in[8];

    float* out      = (float*)d_out;
    float* attn_out = out;
    float* wbuf     = out + (size_t)MTOK * EMB;

    float* datt, * dhsr, * dwq, * dwk, * dwv, * dwo;
    cudaGetSymbolAddress((void**)&datt, g_att);
    cudaGetSymbolAddress((void**)&dhsr, g_hsr);
    cudaGetSymbolAddress((void**)&dwq,  g_wq);
    cudaGetSymbolAddress((void**)&dwk,  g_wk);
    cudaGetSymbolAddress((void**)&dwv,  g_wv);
    cudaGetSymbolAddress((void**)&dwo,  g_wo);

    const int smem_gemm  = (3 * 128 * PAD + 3 * 128 * PAD) * 4;                 // 110592
    const int smem_rsum  = (2 * 64 * KSTR) * 4;                                 // 40960
    const int smem_flash = (2 * 64 * KSTR + 2 * 64 * VSTR + 32 * PSBLK) * 4;    // 98816

    cudaFuncSetAttribute(gemm_qkv_tc, cudaFuncAttributeMaxDynamicSharedMemorySize, smem_gemm);
    cudaFuncSetAttribute(gemm_out_tc, cudaFuncAttributeMaxDynamicSharedMemorySize, smem_gemm);
    cudaFuncSetAttribute(rowsum_tc,   cudaFuncAttributeMaxDynamicSharedMemorySize, smem_rsum);
    cudaFuncSetAttribute(flash_pv_tc, cudaFuncAttributeMaxDynamicSharedMemorySize, smem_flash);

    const int n4_hs = MTOK * EMB / 4;
    const int n4_w  = EMB * EMB / 4;
    const int n4_total = n4_hs + 4 * n4_w;
    round_all_kernel<<<(n4_total + 255) / 256, 256>>>(
        (const float4*)hs, (const float4*)Wq, (const float4*)Wk,
        (const float4*)Wv, (const float4*)Wo,
        (float4*)dhsr, (float4*)dwq, (float4*)dwk, (float4*)dwv, (float4*)dwo,
        n4_hs, n4_w);

    gemm_qkv_tc<<<dim3(EMB / 128, MTOK / 128, 3), 256, smem_gemm>>>(dhsr, bq, bk, bv);

    rowsum_tc<<<dim3(SEQ / 128, BH), 256, smem_rsum>>>();

    flash_pv_tc<<<dim3(SEQ / 64, BH), 256, smem_flash>>>(wbuf);

    gemm_out_tc<<<dim3(EMB / 128, MTOK / 128), 256, smem_gemm>>>(datt, bo, attn_out);
}

// round 16
// speedup vs baseline: 1.0433x; 1.0267x over previous
#include <cuda_runtime.h>
#include <cuda_bf16.h>
#include <math.h>
#include <stdint.h>

// ---------------------------------------------------------------------------
// ViT attention: TF32 mma.sync, pre-rounded tf32 operands, PI-permuted
// Q/K head-dim layouts and transposed V, flash with 128-row q-tiles
// (K/V/Ps crossbar bytes amortized 2x), fragment-major P staging,
// single-sync cp.async pipelines, fused launches.
// B=4, S=2048, E=768, H=12, D=64.
// d_out = attn_output [4,2048,768] ++ attn_weights [4,12,2048,2048].
//
// pi (within each 16-group of a contraction dim): pos(d) = 4*(d&3) + (d>>2).
// ---------------------------------------------------------------------------

#define BATCH     4
#define SEQ       2048
#define EMB       768
#define HEADS     12
#define HDIM      64
#define MTOK      (BATCH * SEQ)
#define BH        (BATCH * HEADS)
#define SCALE_F   0.125f

#define PAD       36      // projection smem stride
#define KSTR      80      // K tile stride: 80 % 32 == 16 -> LDS.128 conflict-free
#define VSTR      80      // V^T tile stride
#define PSBLK     132     // Ps words per (mt,chunk) block

// Scratch (device globals). All tf32-rounded.
// g_q/g_k pi-permuted along d. g_v TRANSPOSED [B][EMB][SEQ], s pi-permuted.
__device__ float g_q[MTOK * EMB];
__device__ float g_k[MTOK * EMB];
__device__ float g_v[MTOK * EMB];
__device__ float g_att[MTOK * EMB];
__device__ float g_inv[BH * SEQ];
__device__ float g_hsr[MTOK * EMB];
__device__ float g_wq[EMB * EMB];
__device__ float g_wk[EMB * EMB];
__device__ float g_wv[EMB * EMB];
__device__ float g_wo[EMB * EMB];

// ---------------------------------------------------------------------------
__device__ __forceinline__ void cp16(void* s, const void* g) {
    uint32_t sa = (uint32_t)__cvta_generic_to_shared(s);
    asm volatile("cp.async.cg.shared.global [%0], [%1], 16;\n" :: "r"(sa), "l"(g));
}
__device__ __forceinline__ void cp_commit() {
    asm volatile("cp.async.commit_group;\n" ::: "memory");
}
__device__ __forceinline__ void cp_wait1() {
    asm volatile("cp.async.wait_group 1;\n" ::: "memory");
}
__device__ __forceinline__ void cp_wait0() {
    asm volatile("cp.async.wait_group 0;\n" ::: "memory");
}

__device__ __forceinline__ float rnd(float x) {
    float r;
    asm("cvt.rna.tf32.f32 %0, %1;" : "=f"(r) : "f"(x));
    return r;
}
__device__ __forceinline__ uint32_t raw(float x) { return __float_as_uint(x); }

__device__ __forceinline__ void mma_tf32(float c[4],
                                         uint32_t a0, uint32_t a1, uint32_t a2, uint32_t a3,
                                         uint32_t b0, uint32_t b1) {
    asm volatile(
        "mma.sync.aligned.m16n8k8.row.col.f32.tf32.tf32.f32 "
        "{%0,%1,%2,%3}, {%4,%5,%6,%7}, {%8,%9}, {%0,%1,%2,%3};\n"
        : "+f"(c[0]), "+f"(c[1]), "+f"(c[2]), "+f"(c[3])
        : "r"(a0), "r"(a1), "r"(a2), "r"(a3), "r"(b0), "r"(b1));
}

// ---------------------------------------------------------------------------
// Fused pre-round: hs + 4 weight matrices, one launch.
// ---------------------------------------------------------------------------
__global__ void round_all_kernel(const float4* __restrict__ hs,
                                 const float4* __restrict__ wq,
                                 const float4* __restrict__ wk,
                                 const float4* __restrict__ wv,
                                 const float4* __restrict__ wo,
                                 float4* __restrict__ dhsr,
                                 float4* __restrict__ dwq,
                                 float4* __restrict__ dwk,
                                 float4* __restrict__ dwv,
                                 float4* __restrict__ dwo,
                                 int n4_hs, int n4_w) {
    int i = blockIdx.x * blockDim.x + threadIdx.x;
    const float4* in;
    float4* out;
    int j = i;
    if (j < n4_hs)            { in = hs; out = dhsr; }
    else if ((j -= n4_hs) < n4_w)  { in = wq; out = dwq; }
    else if ((j -= n4_w) < n4_w)   { in = wk; out = dwk; }
    else if ((j -= n4_w) < n4_w)   { in = wv; out = dwv; }
    else if ((j -= n4_w) < n4_w)   { in = wo; out = dwo; }
    else return;
    float4 v = in[j];
    v.x = rnd(v.x); v.y = rnd(v.y); v.z = rnd(v.z); v.w = rnd(v.w);
    out[j] = v;
}

// ---------------------------------------------------------------------------
// Shared GEMM mainloop body (unchanged). Epilogue mode: 0 plain fp32;
// 1 rounded + pi(n); 2 rounded transposed + pi(s).
// ---------------------------------------------------------------------------
__device__ __forceinline__ void gemm_body(const float* __restrict__ A,
                                          const float* __restrict__ W,
                                          const float* __restrict__ bias,
                                          float* __restrict__ C,
                                          int M, int N, int K,
                                          int m0, int n0, int mode,
                                          float* sm) {
    float (*As)[128][PAD] = (float (*)[128][PAD])sm;
    float (*Ws)[128][PAD] = (float (*)[128][PAD])(sm + 3 * 128 * PAD);

    const int tid = threadIdx.x;
    const int wid = tid >> 5;
    const int lane = tid & 31;
    const int wm = (wid >> 1) * 32;
    const int wn = (wid & 1) * 64;
    const int g = lane >> 2;
    const int t = lane & 3;
    const int nk = K >> 5;

    float acc[2][8][4] = {};

    #pragma unroll
    for (int s = 0; s < 2; s++) {
        const int k0 = s * 32;
        #pragma unroll
        for (int i = 0; i < 4; i++) {
            int idx = tid + i * 256, r = idx >> 3, c4 = idx & 7;
            cp16(&As[s][r][c4 * 4], A + (size_t)(m0 + r) * K + k0 + c4 * 4);
        }
        #pragma unroll
        for (int i = 0; i < 4; i++) {
            int idx = tid + i * 256, r = idx >> 3, c4 = idx & 7;
            cp16(&Ws[s][r][c4 * 4], W + (size_t)(n0 + r) * K + k0 + c4 * 4);
        }
        cp_commit();
    }

    for (int kt = 0; kt < nk; kt++) {
        cp_wait1();
        __syncthreads();

        if (kt + 2 < nk) {
            const int sb = (kt + 2) % 3;
            const int k0 = (kt + 2) * 32;
            #pragma unroll
            for (int i = 0; i < 4; i++) {
                int idx = tid + i * 256, r = idx >> 3, c4 = idx & 7;
                cp16(&As[sb][r][c4 * 4], A + (size_t)(m0 + r) * K + k0 + c4 * 4);
            }
            #pragma unroll
            for (int i = 0; i < 4; i++) {
                int idx = tid + i * 256, r = idx >> 3, c4 = idx & 7;
                cp16(&Ws[sb][r][c4 * 4], W + (size_t)(n0 + r) * K + k0 + c4 * 4);
            }
        }
        cp_commit();

        const int buf = kt % 3;
        #pragma unroll
        for (int kk = 0; kk < 4; kk++) {
            const int kb = kk * 8;
            uint32_t a[2][4], b[8][2];
            #pragma unroll
            for (int mi = 0; mi < 2; mi++) {
                int row = wm + mi * 16;
                a[mi][0] = raw(As[buf][row + g][kb + t]);
                a[mi][1] = raw(As[buf][row + 8 + g][kb + t]);
                a[mi][2] = raw(As[buf][row + g][kb + 4 + t]);
                a[mi][3] = raw(As[buf][row + 8 + g][kb + 4 + t]);
            }
            #pragma unroll
            for (int ni = 0; ni < 8; ni++) {
                int col = wn + ni * 8;
                b[ni][0] = raw(Ws[buf][col + g][kb + t]);
                b[ni][1] = raw(Ws[buf][col + g][kb + 4 + t]);
            }
            #pragma unroll
            for (int mi = 0; mi < 2; mi++)
                #pragma unroll
                for (int ni = 0; ni < 8; ni++)
                    mma_tf32(acc[mi][ni], a[mi][0], a[mi][1], a[mi][2], a[mi][3],
                             b[ni][0], b[ni][1]);
        }
    }

    #pragma unroll
    for (int mi = 0; mi < 2; mi++) {
        #pragma unroll
        for (int ni = 0; ni < 8; ni++) {
            int m = m0 + wm + mi * 16 + g;
            int n = n0 + wn + ni * 8 + t * 2;
            float b0 = __ldg(&bias[n]), b1 = __ldg(&bias[n + 1]);
            float v0 = acc[mi][ni][0] + b0;
            float v1 = acc[mi][ni][1] + b1;
            float v2 = acc[mi][ni][2] + b0;
            float v3 = acc[mi][ni][3] + b1;
            if (mode == 0) {
                C[(size_t)m * N + n]           = v0;
                C[(size_t)m * N + n + 1]       = v1;
                C[(size_t)(m + 8) * N + n]     = v2;
                C[(size_t)(m + 8) * N + n + 1] = v3;
            } else if (mode == 2) {
                int bb = m >> 11, s = m & 2047;
                int sp = (s & ~15) + 4 * (s & 3) + ((s >> 2) & 3);
                C[((size_t)bb * EMB + n) * SEQ + sp]         = rnd(v0);
                C[((size_t)bb * EMB + n + 1) * SEQ + sp]     = rnd(v1);
                C[((size_t)bb * EMB + n) * SEQ + sp + 2]     = rnd(v2);
                C[((size_t)bb * EMB + n + 1) * SEQ + sp + 2] = rnd(v3);
            } else {
                int p0 = (n & ~15) + 4 * (n & 3) + ((n >> 2) & 3);
                int p1 = p0 + 4;
                C[(size_t)m * N + p0]       = rnd(v0);
                C[(size_t)m * N + p1]       = rnd(v1);
                C[(size_t)(m + 8) * N + p0] = rnd(v2);
                C[(size_t)(m + 8) * N + p1] = rnd(v3);
            }
        }
    }
}

__global__ __launch_bounds__(256, 2)
void gemm_qkv_tc(const float* __restrict__ A,
                 const float* __restrict__ bq,
                 const float* __restrict__ bk,
                 const float* __restrict__ bv) {
    extern __shared__ __align__(16) float sm[];
    const int z = blockIdx.z;
    const float* W    = (z == 0) ? g_wq : (z == 1) ? g_wk : g_wv;
    const float* bias = (z == 0) ? bq   : (z == 1) ? bk   : bv;
    float* C          = (z == 0) ? g_q  : (z == 1) ? g_k  : g_v;
    const int mode    = (z == 2) ? 2 : 1;
    gemm_body(A, W, bias, C, MTOK, EMB, EMB,
              blockIdx.y * 128, blockIdx.x * 128, mode, sm);
}

__global__ __launch_bounds__(256, 2)
void gemm_out_tc(const float* __restrict__ A,
                 const float* __restrict__ bias,
                 float* __restrict__ C) {
    extern __shared__ __align__(16) float sm[];
    gemm_body(A, g_wo, bias, C, MTOK, EMB, EMB,
              blockIdx.y * 128, blockIdx.x * 128, 0, sm);
}

// ---------------------------------------------------------------------------
// Q a-fragments (pi-permuted g_q): LDG.128.
// ---------------------------------------------------------------------------
__device__ __forceinline__ void load_q_frags(uint32_t qa[2][8][4],
                                             int b, int h, int qbase,
                                             int g, int t) {
    #pragma unroll
    for (int mi = 0; mi < 2; mi++) {
        const float* qp = g_q + (size_t)(b * SEQ + qbase + mi * 16) * EMB + h * HDIM;
        #pragma unroll
        for (int g16 = 0; g16 < 4; g16++) {
            int c = g16 * 16 + 4 * t;
            float4 lo = *(const float4*)&qp[(size_t)g * EMB + c];
            float4 hi = *(const float4*)&qp[(size_t)(8 + g) * EMB + c];
            qa[mi][2 * g16][0]     = raw(lo.x);
            qa[mi][2 * g16][1]     = raw(hi.x);
            qa[mi][2 * g16][2]     = raw(lo.y);
            qa[mi][2 * g16][3]     = raw(hi.y);
            qa[mi][2 * g16 + 1][0] = raw(lo.z);
            qa[mi][2 * g16 + 1][1] = raw(hi.z);
            qa[mi][2 * g16 + 1][2] = raw(lo.w);
            qa[mi][2 * g16 + 1][3] = raw(hi.w);
        }
    }
}

// ---------------------------------------------------------------------------
// rowsum: unchanged from R15 (128q, Q regs, K LDS.128).
// ---------------------------------------------------------------------------
__global__ __launch_bounds__(256, 2)
void rowsum_tc() {
    extern __shared__ __align__(16) float sm[];
    float* Ks = sm;                       // [2][64][KSTR]
    __shared__ float s_red[128];

    const int bh = blockIdx.y;
    const int b  = bh / HEADS;
    const int h  = bh % HEADS;
    const int q0 = blockIdx.x * 128;
    const int tid = threadIdx.x;
    const int wid = tid >> 5;
    const int lane = tid & 31;
    const int wm = (wid >> 1) * 32;
    const int wn = (wid & 1) * 32;
    const int g = lane >> 2;
    const int t = lane & 3;

    if (tid < 128) s_red[tid] = 0.f;

    #pragma unroll
    for (int i = 0; i < 4; i++) {
        int idx = tid + i * 256, r = idx >> 4, c4 = idx & 15;
        cp16(&Ks[r * KSTR + c4 * 4],
             g_k + (size_t)(b * SEQ + r) * EMB + h * HDIM + c4 * 4);
    }
    cp_commit();

    uint32_t qa[2][8][4];
    load_q_frags(qa, b, h, q0 + wm, g, t);

    float rsum[2][2] = {};

    for (int kt = 0; kt < SEQ / 64; kt++) {
        cp_wait0();
        __syncthreads();

        if (kt + 1 < SEQ / 64) {
            float* Kn = Ks + ((kt + 1) & 1) * 64 * KSTR;
            const int r0 = (kt + 1) * 64;
            #pragma unroll
            for (int i = 0; i < 4; i++) {
                int idx = tid + i * 256, r = idx >> 4, c4 = idx & 15;
                cp16(&Kn[r * KSTR + c4 * 4],
                     g_k + (size_t)(b * SEQ + r0 + r) * EMB + h * HDIM + c4 * 4);
            }
            cp_commit();
        }

        const float* Kb = Ks + (kt & 1) * 64 * KSTR;
        float acc[2][4][4] = {};

        #pragma unroll
        for (int g16 = 0; g16 < 4; g16++) {
            float4 kv[4];
            #pragma unroll
            for (int ni = 0; ni < 4; ni++) {
                int col = wn + ni * 8;
                kv[ni] = *(const float4*)&Kb[(col + g) * KSTR + g16 * 16 + 4 * t];
            }
            #pragma unroll
            for (int sub = 0; sub < 2; sub++) {
                const int d8 = 2 * g16 + sub;
                #pragma unroll
                for (int mi = 0; mi < 2; mi++)
                    #pragma unroll
                    for (int ni = 0; ni < 4; ni++) {
                        uint32_t b0 = raw(sub ? kv[ni].z : kv[ni].x);
                        uint32_t b1 = raw(sub ? kv[ni].w : kv[ni].y);
                        mma_tf32(acc[mi][ni],
                                 qa[mi][d8][0], qa[mi][d8][1], qa[mi][d8][2], qa[mi][d8][3],
                                 b0, b1);
                    }
            }
        }

        #pragma unroll
        for (int mi = 0; mi < 2; mi++)
            #pragma unroll
            for (int ni = 0; ni < 4; ni++) {
                rsum[mi][0] += __expf(acc[mi][ni][0] * SCALE_F)
                             + __expf(acc[mi][ni][1] * SCALE_F);
                rsum[mi][1] += __expf(acc[mi][ni][2] * SCALE_F)
                             + __expf(acc[mi][ni][3] * SCALE_F);
            }
    }

    #pragma unroll
    for (int mi = 0; mi < 2; mi++)
        #pragma unroll
        for (int j = 0; j < 2; j++) {
            rsum[mi][j] += __shfl_xor_sync(0xffffffffu, rsum[mi][j], 1);
            rsum[mi][j] += __shfl_xor_sync(0xffffffffu, rsum[mi][j], 2);
        }

    if (t == 0) {
        #pragma unroll
        for (int mi = 0; mi < 2; mi++) {
            atomicAdd(&s_red[wm + mi * 16 + g],     rsum[mi][0]);
            atomicAdd(&s_red[wm + mi * 16 + 8 + g], rsum[mi][1]);
        }
    }
    __syncthreads();
    if (tid < 128)
        g_inv[(size_t)bh * SEQ + q0 + tid] = 1.0f / s_red[tid];
}

// ---------------------------------------------------------------------------
// flash, 128-row q-tile. 8 warps = 4 wm-groups (32q) x 2 wn (32k / 32d).
// scores per-ni with immediate exp/STG/STS epilogue (small acc_s);
// PV: a LDS.128 from Ps, b LDS.128 from pi'd V^T. Named barrier per wm group
// (2 warps, 64 threads).
// grid (SEQ/128, BH).
// ---------------------------------------------------------------------------
__global__ __launch_bounds__(256, 2)
void flash_pv_tc(float* __restrict__ wbuf) {
    extern __shared__ __align__(16) float sm[];
    float* Ks = sm;                               // [2][64][KSTR]
    float* Vs = Ks + 2 * 64 * KSTR;               // [2][64 d][VSTR s]
    float* Ps = Vs + 2 * 64 * VSTR;               // [64][PSBLK]  (8 mt x 8 chunks)

    const int bh = blockIdx.y;
    const int b  = bh / HEADS;
    const int h  = bh % HEADS;
    const int q0 = blockIdx.x * 128;
    const int tid = threadIdx.x;
    const int wid = tid >> 5;
    const int lane = tid & 31;
    const int wm = (wid >> 1) * 32;     // 4 groups of 32 q-rows
    const int wn = (wid & 1) * 32;      // 2 halves of 32 k-cols / d-cols
    const int g = lane >> 2;
    const int t = lane & 3;
    const int grp_bar = 1 + (wid >> 1); // 4 named barriers, 64 threads each

    const float* vt = g_v + ((size_t)b * EMB + h * HDIM) * SEQ;

    #pragma unroll
    for (int i = 0; i < 4; i++) {
        int idx = tid + i * 256, r = idx >> 4, c4 = idx & 15;
        cp16(&Ks[r * KSTR + c4 * 4],
             g_k + (size_t)(b * SEQ + r) * EMB + h * HDIM + c4 * 4);
        cp16(&Vs[r * VSTR + c4 * 4], vt + (size_t)r * SEQ + c4 * 4);
    }
    cp_commit();

    uint32_t qa[2][8][4];
    load_q_frags(qa, b, h, q0 + wm, g, t);

    float iv[2][2];
    #pragma unroll
    for (int mi = 0; mi < 2; mi++) {
        iv[mi][0] = g_inv[(size_t)bh * SEQ + q0 + wm + mi * 16 + g];
        iv[mi][1] = g_inv[(size_t)bh * SEQ + q0 + wm + mi * 16 + 8 + g];
    }

    float* prow = wbuf + (size_t)bh * SEQ * SEQ;
    float acc_o[2][4][4] = {};          // 32q x 32d (d = wn + dcol*8)

    const int tp0 = (2 * t) & 3;
    const int tp1 = (2 * t + 1) & 3;
    const int j0  = 2 * (t >> 1);
    const int mtb = wm >> 4;            // base mt for this group (0,2,4,6)

    for (int kt = 0; kt < SEQ / 64; kt++) {
        cp_wait0();
        __syncthreads();

        if (kt + 1 < SEQ / 64) {
            const int nb = (kt + 1) & 1;
            const int r0 = (kt + 1) * 64;
            float* Kn = Ks + nb * 64 * KSTR;
            float* Vn = Vs + nb * 64 * VSTR;
            #pragma unroll
            for (int i = 0; i < 4; i++) {
                int idx = tid + i * 256, r = idx >> 4, c4 = idx & 15;
                cp16(&Kn[r * KSTR + c4 * 4],
                     g_k + (size_t)(b * SEQ + r0 + r) * EMB + h * HDIM + c4 * 4);
                cp16(&Vn[r * VSTR + c4 * 4], vt + (size_t)r * SEQ + r0 + c4 * 4);
            }
            cp_commit();
        }

        const float* Kb = Ks + (kt & 1) * 64 * KSTR;
        const float* Vb = Vs + (kt & 1) * 64 * VSTR;

        // scores: 4 ni of 8 k-cols each, immediate epilogue per ni
        #pragma unroll
        for (int ni = 0; ni < 4; ni++) {
            const int col = wn + ni * 8;
            float acc_s[2][4] = {};
            #pragma unroll
            for (int g16 = 0; g16 < 4; g16++) {
                float4 kv = *(const float4*)&Kb[(col + g) * KSTR + g16 * 16 + 4 * t];
                #pragma unroll
                for (int sub = 0; sub < 2; sub++) {
                    const int d8 = 2 * g16 + sub;
                    uint32_t b0 = raw(sub ? kv.z : kv.x);
                    uint32_t b1 = raw(sub ? kv.w : kv.y);
                    #pragma unroll
                    for (int mi = 0; mi < 2; mi++)
                        mma_tf32(acc_s[mi],
                                 qa[mi][d8][0], qa[mi][d8][1], qa[mi][d8][2], qa[mi][d8][3],
                                 b0, b1);
                }
            }
            const int chunk = (wn >> 3) + ni;
            #pragma unroll
            for (int mi = 0; mi < 2; mi++) {
                const int mt = mtb + mi;
                const int r0g = q0 + wm + mi * 16 + g;
                const int c0 = col + 2 * t;
                float p00 = rnd(__expf(acc_s[mi][0] * SCALE_F) * iv[mi][0]);
                float p01 = rnd(__expf(acc_s[mi][1] * SCALE_F) * iv[mi][0]);
                float p10 = rnd(__expf(acc_s[mi][2] * SCALE_F) * iv[mi][1]);
                float p11 = rnd(__expf(acc_s[mi][3] * SCALE_F) * iv[mi][1]);
                *(float2*)&prow[(size_t)r0g * SEQ + kt * 64 + c0]       = make_float2(p00, p01);
                *(float2*)&prow[(size_t)(r0g + 8) * SEQ + kt * 64 + c0] = make_float2(p10, p11);
                float* pb = &Ps[(mt * 8 + chunk) * PSBLK];
                *(float2*)&pb[(g * 4 + tp0) * 4 + j0] = make_float2(p00, p10);
                *(float2*)&pb[(g * 4 + tp1) * 4 + j0] = make_float2(p01, p11);
            }
        }
        asm volatile("bar.sync %0, 64;" :: "r"(grp_bar) : "memory");

        // O += p @ V : per s16, vv[4] (d cols) + a per (sub, mi)
        #pragma unroll
        for (int s16 = 0; s16 < 4; s16++) {
            float4 vv[4];
            #pragma unroll
            for (int dcol = 0; dcol < 4; dcol++) {
                int drow = wn + dcol * 8 + g;
                vv[dcol] = *(const float4*)&Vb[drow * VSTR + s16 * 16 + 4 * t];
            }
            #pragma unroll
            for (int sub = 0; sub < 2; sub++) {
                const int d8 = 2 * s16 + sub;
                uint32_t a[2][4];
                #pragma unroll
                for (int mi = 0; mi < 2; mi++) {
                    float4 av = *(const float4*)&Ps[((mtb + mi) * 8 + d8) * PSBLK + lane * 4];
                    a[mi][0] = raw(av.x);
                    a[mi][1] = raw(av.y);
                    a[mi][2] = raw(av.z);
                    a[mi][3] = raw(av.w);
                }
                #pragma unroll
                for (int mi = 0; mi < 2; mi++)
                    #pragma unroll
                    for (int dcol = 0; dcol < 4; dcol++) {
                        uint32_t b0 = raw(sub ? vv[dcol].z : vv[dcol].x);
                        uint32_t b1 = raw(sub ? vv[dcol].w : vv[dcol].y);
                        mma_tf32(acc_o[mi][dcol], a[mi][0], a[mi][1], a[mi][2], a[mi][3],
                                 b0, b1);
                    }
            }
        }
        asm volatile("bar.sync %0, 64;" :: "r"(grp_bar) : "memory");
    }

    #pragma unroll
    for (int mi = 0; mi < 2; mi++) {
        #pragma unroll
        for (int dcol = 0; dcol < 4; dcol++) {
            int m = q0 + wm + mi * 16 + g;
            int d = wn + dcol * 8 + t * 2;
            g_att[(size_t)(b * SEQ + m) * EMB + h * HDIM + d]         = rnd(acc_o[mi][dcol][0]);
            g_att[(size_t)(b * SEQ + m) * EMB + h * HDIM + d + 1]     = rnd(acc_o[mi][dcol][1]);
            g_att[(size_t)(b * SEQ + m + 8) * EMB + h * HDIM + d]     = rnd(acc_o[mi][dcol][2]);
            g_att[(size_t)(b * SEQ + m + 8) * EMB + h * HDIM + d + 1] = rnd(acc_o[mi][dcol][3]);
        }
    }
}

// ---------------------------------------------------------------------------
// launch
// ---------------------------------------------------------------------------
extern "C" void kernel_launch(void* const* d_in, const int* in_sizes, int n_in,
                              void* d_out, int out_size) {
    (void)in_sizes; (void)n_in; (void)out_size;

    const float* hs = (const float*)d_in[0];
    const float* Wq = (const float*)d_in[1];
    const float* bq = (const float*)d_in[2];
    const float* Wk = (const float*)d_in[3];
    const float* bk = (const float*)d_in[4];
    const float* Wv = (const float*)d_in[5];
    const float* bv = (const float*)d_in[6];
    const float* Wo = (const float*)d_in[7];
    const float* bo = (const float*)d_in[8];

    float* out      = (float*)d_out;
    float* attn_out = out;
    float* wbuf     = out + (size_t)MTOK * EMB;

    float* datt, * dhsr, * dwq, * dwk, * dwv, * dwo;
    cudaGetSymbolAddress((void**)&datt, g_att);
    cudaGetSymbolAddress((void**)&dhsr, g_hsr);
    cudaGetSymbolAddress((void**)&dwq,  g_wq);
    cudaGetSymbolAddress((void**)&dwk,  g_wk);
    cudaGetSymbolAddress((void**)&dwv,  g_wv);
    cudaGetSymbolAddress((void**)&dwo,  g_wo);

    const int smem_gemm  = (3 * 128 * PAD + 3 * 128 * PAD) * 4;                 // 110592
    const int smem_rsum  = (2 * 64 * KSTR) * 4;                                 // 40960
    const int smem_flash = (2 * 64 * KSTR + 2 * 64 * VSTR + 64 * PSBLK) * 4;    // 115712

    cudaFuncSetAttribute(gemm_qkv_tc, cudaFuncAttributeMaxDynamicSharedMemorySize, smem_gemm);
    cudaFuncSetAttribute(gemm_out_tc, cudaFuncAttributeMaxDynamicSharedMemorySize, smem_gemm);
    cudaFuncSetAttribute(rowsum_tc,   cudaFuncAttributeMaxDynamicSharedMemorySize, smem_rsum);
    cudaFuncSetAttribute(flash_pv_tc, cudaFuncAttributeMaxDynamicSharedMemorySize, smem_flash);

    const int n4_hs = MTOK * EMB / 4;
    const int n4_w  = EMB * EMB / 4;
    const int n4_total = n4_hs + 4 * n4_w;
    round_all_kernel<<<(n4_total + 255) / 256, 256>>>(
        (const float4*)hs, (const float4*)Wq, (const float4*)Wk,
        (const float4*)Wv, (const float4*)Wo,
        (float4*)dhsr, (float4*)dwq, (float4*)dwk, (float4*)dwv, (float4*)dwo,
        n4_hs, n4_w);

    gemm_qkv_tc<<<dim3(EMB / 128, MTOK / 128, 3), 256, smem_gemm>>>(dhsr, bq, bk, bv);

    rowsum_tc<<<dim3(SEQ / 128, BH), 256, smem_rsum>>>();

    flash_pv_tc<<<dim3(SEQ / 128, BH), 256, smem_flash>>>(wbuf);

    gemm_out_tc<<<dim3(EMB / 128, MTOK / 128), 256, smem_gemm>>>(datt, bo, attn_out);
}